// round 4
// baseline (speedup 1.0000x reference)
#include <cuda_runtime.h>
#include <stdint.h>

// Problem constants (match reference)
#define HOP        160
#define FFT        1024
#define NUM_LABELS 72
#define BATCH      4
#define TLEN       240000
#define PAD        (FFT / 2)           // 512
#define LPAD       (TLEN + 2 * PAD)    // 241024
#define NOUT       ((LPAD - FFT) / HOP + 1)  // 1501

#define THREADS 256

__global__ void __launch_bounds__(THREADS)
label_majority_kernel(const int* __restrict__ lbl, float* __restrict__ out)
{
    const int w = blockIdx.x;   // window index 0..NOUT-1
    const int b = blockIdx.y;   // batch row

    __shared__ int hist[NUM_LABELS];

    const int tid = threadIdx.x;
    if (tid < NUM_LABELS) hist[tid] = 0;
    __syncthreads();

    const int* __restrict__ row = lbl + (size_t)b * TLEN;
    const int start = w * HOP;  // padded-coordinate window start

    // Each thread handles 4 positions, stride THREADS -> coalesced 4B loads.
    #pragma unroll
    for (int k = 0; k < FFT / THREADS; k++) {
        int j = start + tid + k * THREADS;   // padded index, < LPAD always
        int o = j - PAD;                     // map reflect padding to source index
        if (o < 0) o = -o;                                  // left reflect (excl. edge)
        else if (o >= TLEN) o = 2 * (TLEN - 1) - o;         // right reflect
        int v = row[o];
        atomicAdd(&hist[v], 1);
    }
    __syncthreads();

    // Argmax over 72 bins, tie-break = lowest label (matches jnp.argmax).
    // Pack: count (<=1024) << 7 | (127 - label). Max packed => max count,
    // ties resolved toward smaller label.
    int packed = -1;
    if (tid < NUM_LABELS) {
        packed = (hist[tid] << 7) | (127 - tid);
    }
    // Warp max
    #pragma unroll
    for (int off = 16; off > 0; off >>= 1)
        packed = max(packed, __shfl_xor_sync(0xFFFFFFFFu, packed, off));

    __shared__ int warp_max[THREADS / 32];
    if ((tid & 31) == 0) warp_max[tid >> 5] = packed;
    __syncthreads();

    if (tid == 0) {
        int m = warp_max[0];
        #pragma unroll
        for (int i = 1; i < THREADS / 32; i++) m = max(m, warp_max[i]);
        out[(size_t)b * NOUT + w] = (float)(127 - (m & 127));
    }
}

extern "C" void kernel_launch(void* const* d_in, const int* in_sizes, int n_in,
                              void* d_out, int out_size)
{
    const int* lbl = (const int*)d_in[0];   // [B, T] int32
    // d_in[1] is the all-ones conv weight: irrelevant (window sum == histogram).
    float* out = (float*)d_out;             // [B, NOUT], compared as float32

    dim3 grid(NOUT, BATCH);
    label_majority_kernel<<<grid, THREADS>>>(lbl, out);
}